// round 1
// baseline (speedup 1.0000x reference)
#include <cuda_runtime.h>

// Problem constants
#define BB   8
#define CIN  64
#define CO   128
#define LL   18
#define LV   16
#define HW   1024
#define NH   2

// Scratch (device globals; no allocations allowed)
__device__ float g_Q[(size_t)BB*CO*LL*HW];      // 75.5 MB
__device__ float g_K[(size_t)BB*CO*LL*HW];      // 75.5 MB
__device__ float g_V[(size_t)BB*CO*LV*HW];      // 67 MB
__device__ float g_lp[(size_t)9*BB*NH*CO*CO];   // 9.4 MB split-K partials
__device__ float g_attn[(size_t)BB*NH*CO*CO];   // 1 MB

// ---------------------------------------------------------------------------
// Conv 1x3x3, pad (0,1,1): implicit GEMM  O[128co, 128hw] tile, K = 64*9 = 576
// which==0 -> write g_Q (scale 0.5), which==1 -> write g_K (scale 1.0)
// grid: (8 hw-tiles, B*L slices)
// ---------------------------------------------------------------------------
__global__ __launch_bounds__(256) void conv2d_k(const float* __restrict__ x,
                                                const float* __restrict__ w,
                                                const float* __restrict__ bias,
                                                int which, float scale) {
    const int p0 = blockIdx.x * 128;
    const int slice = blockIdx.y;
    const int b = slice / LL, l = slice % LL;
    __shared__ float As[8][128];
    __shared__ float Bs[8][128];
    const int tid = threadIdx.x;
    const int ty = tid >> 4, tx = tid & 15;
    float acc[8][8];
#pragma unroll
    for (int i = 0; i < 8; i++)
#pragma unroll
        for (int j = 0; j < 8; j++) acc[i][j] = 0.f;

    const float* xb = x + (size_t)b * CIN * LL * HW + (size_t)l * HW;

    for (int r0 = 0; r0 < 576; r0 += 8) {
        // A tile: As[kk][co] = w[co*576 + r0+kk]
#pragma unroll
        for (int i = 0; i < 4; i++) {
            int idx = tid + i * 256;
            int kk = idx >> 7, co = idx & 127;
            As[kk][co] = w[co * 576 + r0 + kk];
        }
        // B tile: im2col gather
#pragma unroll
        for (int i = 0; i < 4; i++) {
            int idx = tid + i * 256;
            int kk = idx >> 7, p = idx & 127;
            int r = r0 + kk;
            int ci = r / 9, rem = r % 9;
            int kh = rem / 3, kw = rem % 3;
            int pp = p0 + p;
            int h = pp >> 5, ww = pp & 31;
            int ih = h + kh - 1, iw = ww + kw - 1;
            float v = 0.f;
            if ((unsigned)ih < 32u && (unsigned)iw < 32u)
                v = xb[(size_t)ci * LL * HW + ih * 32 + iw];
            Bs[kk][p] = v;
        }
        __syncthreads();
#pragma unroll
        for (int kk = 0; kk < 8; kk++) {
            float a[8], bb[8];
#pragma unroll
            for (int i = 0; i < 8; i++) a[i] = As[kk][ty * 8 + i];
#pragma unroll
            for (int j = 0; j < 8; j++) bb[j] = Bs[kk][tx * 8 + j];
#pragma unroll
            for (int i = 0; i < 8; i++)
#pragma unroll
                for (int j = 0; j < 8; j++) acc[i][j] += a[i] * bb[j];
        }
        __syncthreads();
    }

    float* out = which ? g_K : g_Q;
#pragma unroll
    for (int i = 0; i < 8; i++) {
        int co = ty * 8 + i;
        float bv = bias[co];
        float* op = out + ((size_t)(b * CO + co) * LL + l) * HW + p0 + tx * 8;
#pragma unroll
        for (int j = 0; j < 8; j++) op[j] = (acc[i][j] + bv) * scale;
    }
}

// ---------------------------------------------------------------------------
// Conv 3x3x3, pad (0,1,1): K = 64*27 = 1728, out depth 16
// grid: (8 hw-tiles, B*16 slices) -> g_V
// ---------------------------------------------------------------------------
__global__ __launch_bounds__(256) void conv3d_k(const float* __restrict__ x,
                                                const float* __restrict__ w,
                                                const float* __restrict__ bias) {
    const int p0 = blockIdx.x * 128;
    const int slice = blockIdx.y;
    const int b = slice >> 4, lo = slice & 15;
    __shared__ float As[8][128];
    __shared__ float Bs[8][128];
    const int tid = threadIdx.x;
    const int ty = tid >> 4, tx = tid & 15;
    float acc[8][8];
#pragma unroll
    for (int i = 0; i < 8; i++)
#pragma unroll
        for (int j = 0; j < 8; j++) acc[i][j] = 0.f;

    const float* xb = x + (size_t)b * CIN * LL * HW;

    for (int r0 = 0; r0 < 1728; r0 += 8) {
#pragma unroll
        for (int i = 0; i < 4; i++) {
            int idx = tid + i * 256;
            int kk = idx >> 7, co = idx & 127;
            As[kk][co] = w[co * 1728 + r0 + kk];
        }
#pragma unroll
        for (int i = 0; i < 4; i++) {
            int idx = tid + i * 256;
            int kk = idx >> 7, p = idx & 127;
            int r = r0 + kk;
            int ci = r / 27, rem = r % 27;
            int kd = rem / 9, rem2 = rem % 9;
            int kh = rem2 / 3, kw = rem2 % 3;
            int pp = p0 + p;
            int h = pp >> 5, ww = pp & 31;
            int ih = h + kh - 1, iw = ww + kw - 1;
            float v = 0.f;
            if ((unsigned)ih < 32u && (unsigned)iw < 32u)
                v = xb[((size_t)ci * LL + lo + kd) * HW + ih * 32 + iw];
            Bs[kk][p] = v;
        }
        __syncthreads();
#pragma unroll
        for (int kk = 0; kk < 8; kk++) {
            float a[8], bb[8];
#pragma unroll
            for (int i = 0; i < 8; i++) a[i] = As[kk][ty * 8 + i];
#pragma unroll
            for (int j = 0; j < 8; j++) bb[j] = Bs[kk][tx * 8 + j];
#pragma unroll
            for (int i = 0; i < 8; i++)
#pragma unroll
                for (int j = 0; j < 8; j++) acc[i][j] += a[i] * bb[j];
        }
        __syncthreads();
    }

#pragma unroll
    for (int i = 0; i < 8; i++) {
        int co = ty * 8 + i;
        float bv = bias[co];
        float* op = g_V + ((size_t)(b * CO + co) * LV + lo) * HW + p0 + tx * 8;
#pragma unroll
        for (int j = 0; j < 8; j++) op[j] = acc[i][j] + bv;
    }
}

// ---------------------------------------------------------------------------
// Logits split-K: one block per (depth-chunk lchunk, b*2+n); C = Q·K^T over
// one depth slice's 1024 hw; partial 128x128 written to g_lp.
// grid: (9, 16)
// ---------------------------------------------------------------------------
__global__ __launch_bounds__(256) void logits_k() {
    const int lchunk = blockIdx.x, bn = blockIdx.y;
    const int b = bn >> 1, n = bn & 1;
    const int l = n * 9 + lchunk;
    const float* Qb = g_Q + ((size_t)b * CO * LL + l) * HW;  // + c*LL*HW
    const float* Kb = g_K + ((size_t)b * CO * LL + l) * HW;
    __shared__ float Qs[32][129];
    __shared__ float Ks[32][129];
    const int tid = threadIdx.x;
    const int ty = tid >> 4, tx = tid & 15;
    float acc[8][8];
#pragma unroll
    for (int i = 0; i < 8; i++)
#pragma unroll
        for (int j = 0; j < 8; j++) acc[i][j] = 0.f;

    for (int hw0 = 0; hw0 < HW; hw0 += 32) {
#pragma unroll
        for (int i = 0; i < 16; i++) {
            int idx = tid + i * 256;
            int c = idx >> 5, kk = idx & 31;
            Qs[kk][c] = Qb[(size_t)c * LL * HW + hw0 + kk];
            Ks[kk][c] = Kb[(size_t)c * LL * HW + hw0 + kk];
        }
        __syncthreads();
#pragma unroll
        for (int kk = 0; kk < 32; kk++) {
            float a[8], bb[8];
#pragma unroll
            for (int i = 0; i < 8; i++) a[i] = Qs[kk][ty * 8 + i];
#pragma unroll
            for (int j = 0; j < 8; j++) bb[j] = Ks[kk][tx * 8 + j];
#pragma unroll
            for (int i = 0; i < 8; i++)
#pragma unroll
                for (int j = 0; j < 8; j++) acc[i][j] += a[i] * bb[j];
        }
        __syncthreads();
    }

    float* lp = g_lp + ((size_t)lchunk * 16 + bn) * CO * CO;
#pragma unroll
    for (int i = 0; i < 8; i++) {
        int c = ty * 8 + i;
#pragma unroll
        for (int j = 0; j < 8; j++) lp[(size_t)c * CO + tx * 8 + j] = acc[i][j];
    }
}

// ---------------------------------------------------------------------------
// Reduce 9 partials + softmax over m. One warp per (bn, c) row. grid 256x256.
// ---------------------------------------------------------------------------
__global__ __launch_bounds__(256) void softmax_k() {
    const int warp = (blockIdx.x * 256 + threadIdx.x) >> 5;
    const int lane = threadIdx.x & 31;
    if (warp >= 16 * CO) return;
    const int bn = warp >> 7, c = warp & 127;
    float v[4];
#pragma unroll
    for (int j = 0; j < 4; j++) {
        int m = lane + j * 32;
        float s = 0.f;
#pragma unroll
        for (int p = 0; p < 9; p++)
            s += g_lp[(((size_t)p * 16 + bn) * CO + c) * CO + m];
        v[j] = s;
    }
    float mx = fmaxf(fmaxf(v[0], v[1]), fmaxf(v[2], v[3]));
#pragma unroll
    for (int o = 16; o; o >>= 1) mx = fmaxf(mx, __shfl_xor_sync(0xffffffffu, mx, o));
    float sum = 0.f;
#pragma unroll
    for (int j = 0; j < 4; j++) { v[j] = __expf(v[j] - mx); sum += v[j]; }
#pragma unroll
    for (int o = 16; o; o >>= 1) sum += __shfl_xor_sync(0xffffffffu, sum, o);
    float inv = 1.f / sum;
#pragma unroll
    for (int j = 0; j < 4; j++)
        g_attn[((size_t)bn * CO + c) * CO + lane + j * 32] = v[j] * inv;
}

// ---------------------------------------------------------------------------
// out[b,c,l,hw] = sum_m attn[b, l/8, c, m] * V[b, m, l, hw]
// grid: (8 hw-tiles, B*16 slices)
// ---------------------------------------------------------------------------
__global__ __launch_bounds__(256) void out_k(float* __restrict__ out) {
    const int p0 = blockIdx.x * 128;
    const int s = blockIdx.y;
    const int b = s >> 4, l = s & 15, n = l >> 3;
    const float* A = g_attn + (size_t)(b * 2 + n) * CO * CO;
    __shared__ float As[32][129];
    __shared__ float Bs[32][128];
    const int tid = threadIdx.x;
    const int ty = tid >> 4, tx = tid & 15;
    float acc[8][8];
#pragma unroll
    for (int i = 0; i < 8; i++)
#pragma unroll
        for (int j = 0; j < 8; j++) acc[i][j] = 0.f;

    for (int m0 = 0; m0 < 128; m0 += 32) {
#pragma unroll
        for (int i = 0; i < 16; i++) {
            int idx = tid + i * 256;
            int c = idx >> 5, mm = idx & 31;
            As[mm][c] = A[(size_t)c * CO + m0 + mm];
        }
#pragma unroll
        for (int i = 0; i < 16; i++) {
            int idx = tid + i * 256;
            int mm = idx >> 7, p = idx & 127;
            Bs[mm][p] = g_V[((size_t)(b * CO + m0 + mm) * LV + l) * HW + p0 + p];
        }
        __syncthreads();
#pragma unroll
        for (int kk = 0; kk < 32; kk++) {
            float a[8], bb[8];
#pragma unroll
            for (int i = 0; i < 8; i++) a[i] = As[kk][ty * 8 + i];
#pragma unroll
            for (int j = 0; j < 8; j++) bb[j] = Bs[kk][tx * 8 + j];
#pragma unroll
            for (int i = 0; i < 8; i++)
#pragma unroll
                for (int j = 0; j < 8; j++) acc[i][j] += a[i] * bb[j];
        }
        __syncthreads();
    }

#pragma unroll
    for (int i = 0; i < 8; i++) {
        int c = ty * 8 + i;
        float* op = out + ((size_t)(b * CO + c) * LV + l) * HW + p0 + tx * 8;
#pragma unroll
        for (int j = 0; j < 8; j++) op[j] = acc[i][j];
    }
}

// ---------------------------------------------------------------------------
extern "C" void kernel_launch(void* const* d_in, const int* in_sizes, int n_in,
                              void* d_out, int out_size) {
    const float* input  = (const float*)d_in[0];
    const float* memory = (const float*)d_in[1];
    const float* wq = (const float*)d_in[2];
    const float* bq = (const float*)d_in[3];
    const float* wk = (const float*)d_in[4];
    const float* bk = (const float*)d_in[5];
    const float* wv = (const float*)d_in[6];
    const float* bv = (const float*)d_in[7];
    float* out = (float*)d_out;

    conv2d_k<<<dim3(8, BB * LL), 256>>>(input,  wq, bq, 0, 0.5f);
    conv2d_k<<<dim3(8, BB * LL), 256>>>(memory, wk, bk, 1, 1.0f);
    conv3d_k<<<dim3(8, BB * LV), 256>>>(memory, wv, bv);
    logits_k<<<dim3(9, 16), 256>>>();
    softmax_k<<<256, 256>>>();
    out_k<<<dim3(8, BB * LV), 256>>>(out);
}

// round 3
// speedup vs baseline: 3.0648x; 3.0648x over previous
#include <cuda_runtime.h>
#include <cuda_bf16.h>
#include <cstdint>

#define BB   8
#define CIN  64
#define CO   128
#define LL   18
#define LV   16
#define HW   1024
#define NH   2

// ---------------- scratch (device globals; no allocation allowed) ----------
__device__ float g_Q[(size_t)BB*CO*LL*HW];
__device__ float g_K[(size_t)BB*CO*LL*HW];
__device__ float g_V[(size_t)BB*CO*LV*HW];
__device__ float g_lp[(size_t)9*BB*NH*CO*CO];
__device__ float g_attn[(size_t)BB*NH*CO*CO];

// transposed split-bf16 inputs: [b][l][hw][ci]  (hi and lo separately)
__device__ __nv_bfloat16 g_hin[(size_t)BB*LL*HW*CIN];
__device__ __nv_bfloat16 g_lin[(size_t)BB*LL*HW*CIN];
__device__ __nv_bfloat16 g_hmm[(size_t)BB*LL*HW*CIN];
__device__ __nv_bfloat16 g_lmm[(size_t)BB*LL*HW*CIN];
// weight tile images, pitch 72 halves: [chunk][co=128][72]
__device__ uint4 g_wqh[9*1152],  g_wql[9*1152];
__device__ uint4 g_wkh[9*1152],  g_wkl[9*1152];
__device__ uint4 g_wvh[27*1152], g_wvl[27*1152];

// ---------------- PTX helpers ----------------------------------------------
__device__ __forceinline__ uint32_t smem_u32(const void* p) {
    uint32_t a;
    asm("{ .reg .u64 t; cvta.to.shared.u64 t, %1; cvt.u32.u64 %0, t; }"
        : "=r"(a) : "l"(p));
    return a;
}
__device__ __forceinline__ void ldmat4(uint32_t& r0, uint32_t& r1, uint32_t& r2,
                                       uint32_t& r3, uint32_t a) {
    asm volatile("ldmatrix.sync.aligned.m8n8.x4.shared.b16 {%0,%1,%2,%3}, [%4];"
                 : "=r"(r0), "=r"(r1), "=r"(r2), "=r"(r3) : "r"(a));
}
__device__ __forceinline__ void ldmat2(uint32_t& r0, uint32_t& r1, uint32_t a) {
    asm volatile("ldmatrix.sync.aligned.m8n8.x2.shared.b16 {%0,%1}, [%2];"
                 : "=r"(r0), "=r"(r1) : "r"(a));
}
__device__ __forceinline__ void mma16816(float* c, const uint32_t* a,
                                         const uint32_t* b) {
    asm volatile(
        "mma.sync.aligned.m16n8k16.row.col.f32.bf16.bf16.f32 "
        "{%0,%1,%2,%3}, {%4,%5,%6,%7}, {%8,%9}, {%0,%1,%2,%3};"
        : "+f"(c[0]), "+f"(c[1]), "+f"(c[2]), "+f"(c[3])
        : "r"(a[0]), "r"(a[1]), "r"(a[2]), "r"(a[3]), "r"(b[0]), "r"(b[1]));
}
__device__ __forceinline__ void cpasync16(uint32_t dst, const void* src, int sz) {
    asm volatile("cp.async.ca.shared.global [%0], [%1], 16, %2;"
                 :: "r"(dst), "l"(src), "r"(sz) : "memory");
}
__device__ __forceinline__ void cp_commit() {
    asm volatile("cp.async.commit_group;" ::: "memory");
}
__device__ __forceinline__ void cp_wait1() {
    asm volatile("cp.async.wait_group 1;" ::: "memory");
}
__device__ __forceinline__ void cp_wait0() {
    asm volatile("cp.async.wait_group 0;" ::: "memory");
}

// ---------------- prep kernels ---------------------------------------------
// transpose + split: x[b][ci][l][hw] -> (hi,lo)[b][l][hw][ci]
__global__ __launch_bounds__(256) void pack_k(const float* __restrict__ x, int dst) {
    __shared__ float tile[64][65];
    const int s = blockIdx.x;            // b*18 + l
    const int hw0 = blockIdx.y * 64;
    const int b = s / LL, l = s % LL;
    __nv_bfloat16* oh = dst ? g_hmm : g_hin;
    __nv_bfloat16* ol = dst ? g_lmm : g_lin;
#pragma unroll
    for (int i = 0; i < 16; i++) {
        int idx = threadIdx.x + i * 256;
        int ci = idx >> 6, hw = idx & 63;
        tile[ci][hw] = x[(((size_t)b * CIN + ci) * LL + l) * HW + hw0 + hw];
    }
    __syncthreads();
#pragma unroll
    for (int i = 0; i < 16; i++) {
        int idx = threadIdx.x + i * 256;
        int hw = idx >> 6, ci = idx & 63;
        float v = tile[ci][hw];
        __nv_bfloat16 h = __float2bfloat16(v);
        size_t o = ((size_t)s * HW + hw0 + hw) * CIN + ci;
        oh[o] = h;
        ol[o] = __float2bfloat16(v - __bfloat162float(h));
    }
}

// weights -> padded pitch-72 images per chunk
__global__ __launch_bounds__(256) void wprep_k(const float* __restrict__ w,
                                               int nchunk, int dst) {
    int i = blockIdx.x * 256 + threadIdx.x;
    if (i >= nchunk * 8192) return;
    int c = i >> 13, r = i & 8191, co = r >> 6, ci = r & 63;
    float v = w[(co * 64 + ci) * nchunk + c];
    __nv_bfloat16 h = __float2bfloat16(v);
    __nv_bfloat16 lo = __float2bfloat16(v - __bfloat162float(h));
    __nv_bfloat16 *oh, *ol;
    if (dst == 0)      { oh = (__nv_bfloat16*)g_wqh; ol = (__nv_bfloat16*)g_wql; }
    else if (dst == 1) { oh = (__nv_bfloat16*)g_wkh; ol = (__nv_bfloat16*)g_wkl; }
    else               { oh = (__nv_bfloat16*)g_wvh; ol = (__nv_bfloat16*)g_wvl; }
    oh[(size_t)c * 9216 + co * 72 + ci] = h;
    ol[(size_t)c * 9216 + co * 72 + ci] = lo;
}

// ---------------- HMMA implicit-GEMM conv ----------------------------------
// smem buffer: Ah[128*72] Al Bh[128*72] Bl  (bf16, 18432 B each) x2 buffers
#define ABYTES 18432
#define BUFSZ  73728
#define SMEMSZ (2*BUFSZ)

__device__ __forceinline__ void issue_chunk(
    int c, int is3d, int p0, int b, int l, uint32_t sb,
    const uint4* wh, const uint4* wl,
    const __nv_bfloat16* xh, const __nv_bfloat16* xl, int tid) {
    int kd, kh, kw;
    if (is3d) { kd = c / 9; int r = c % 9; kh = r / 3; kw = r % 3; }
    else      { kd = 0; kh = c / 3; kw = c % 3; }
    const uint32_t base = sb + (c & 1) * BUFSZ;
    // A: straight copy of pre-padded weight images
#pragma unroll
    for (int i = 0; i < 9; i++) {
        int idx = tid + i * 256;
        if (idx < 2304) {
            int half = idx >= 1152;
            int r = idx - half * 1152;
            const uint4* s = (half ? wl : wh) + (size_t)c * 1152 + r;
            cpasync16(base + half * ABYTES + r * 16, s, 16);
        }
    }
    // B: im2col rows, contiguous 128B per row, zfill OOB
    {
        int row = tid >> 1, sub = tid & 1;
        int pg = p0 + row;
        int ih = (pg >> 5) + kh - 1, iw = (pg & 31) + kw - 1;
        int ok = ((unsigned)ih < 32u) && ((unsigned)iw < 32u);
        int ihc = ok ? ih : 0, iwc = ok ? iw : 0;
        const __nv_bfloat16* s = (sub ? xl : xh) +
            ((size_t)((b * LL + l + kd) * HW) + ihc * 32 + iwc) * CIN;
        uint32_t dst = base + 36864 + sub * ABYTES + row * 144;
        int sz = ok ? 16 : 0;
#pragma unroll
        for (int j = 0; j < 8; j++)
            cpasync16(dst + j * 16, (const char*)s + j * 16, sz);
    }
    cp_commit();
}

__global__ __launch_bounds__(256, 1)
void convmma_k(const float* __restrict__ bias, int mode, int DOUT, int NC,
               int is3d, float scale) {
    extern __shared__ char smem[];
    const uint32_t sb = smem_u32(smem);
    const int tid = threadIdx.x, wid = tid >> 5, lane = tid & 31;
    const int p0 = blockIdx.x * 128;
    const int b = blockIdx.y / DOUT, l = blockIdx.y % DOUT;

    const __nv_bfloat16 *xh, *xl;
    const uint4 *wh, *wl;
    float* out;
    if (mode == 0)      { xh = g_hin; xl = g_lin; wh = g_wqh; wl = g_wql; out = g_Q; }
    else if (mode == 1) { xh = g_hmm; xl = g_lmm; wh = g_wkh; wl = g_wkl; out = g_K; }
    else                { xh = g_hmm; xl = g_lmm; wh = g_wvh; wl = g_wvl; out = g_V; }

    const int co0 = (wid & 1) * 64;       // warp m-offset
    const int p0l = (wid >> 1) * 32;      // warp n-offset

    float acc[4][4][4];
#pragma unroll
    for (int mt = 0; mt < 4; mt++)
#pragma unroll
        for (int nt = 0; nt < 4; nt++)
#pragma unroll
            for (int i = 0; i < 4; i++) acc[mt][nt][i] = 0.f;

    issue_chunk(0, is3d, p0, b, l, sb, wh, wl, xh, xl, tid);

    for (int c = 0; c < NC; c++) {
        if (c + 1 < NC) {
            issue_chunk(c + 1, is3d, p0, b, l, sb, wh, wl, xh, xl, tid);
            cp_wait1();
        } else {
            cp_wait0();
        }
        __syncthreads();
        const uint32_t base = sb + (c & 1) * BUFSZ;
        const uint32_t aAh = base, aAl = base + ABYTES;
        const uint32_t aBh = base + 36864, aBl = base + 36864 + ABYTES;
#pragma unroll
        for (int k = 0; k < 4; k++) {
            uint32_t ah[4][4], al[4][4], bh[4][2], bl[4][2];
#pragma unroll
            for (int mt = 0; mt < 4; mt++) {
                uint32_t off = (uint32_t)(((co0 + mt * 16 + (lane & 15)) * 72 +
                                           k * 16 + (lane >> 4) * 8) * 2);
                ldmat4(ah[mt][0], ah[mt][1], ah[mt][2], ah[mt][3], aAh + off);
                ldmat4(al[mt][0], al[mt][1], al[mt][2], al[mt][3], aAl + off);
            }
#pragma unroll
            for (int nt = 0; nt < 4; nt++) {
                uint32_t off = (uint32_t)(((p0l + nt * 8 + (lane & 7)) * 72 +
                                           k * 16 + ((lane >> 3) & 1) * 8) * 2);
                ldmat2(bh[nt][0], bh[nt][1], aBh + off);
                ldmat2(bl[nt][0], bl[nt][1], aBl + off);
            }
#pragma unroll
            for (int mt = 0; mt < 4; mt++)
#pragma unroll
                for (int nt = 0; nt < 4; nt++)
                    mma16816(acc[mt][nt], ah[mt], bh[nt]);
#pragma unroll
            for (int mt = 0; mt < 4; mt++)
#pragma unroll
                for (int nt = 0; nt < 4; nt++)
                    mma16816(acc[mt][nt], ah[mt], bl[nt]);
#pragma unroll
            for (int mt = 0; mt < 4; mt++)
#pragma unroll
                for (int nt = 0; nt < 4; nt++)
                    mma16816(acc[mt][nt], al[mt], bh[nt]);
        }
        __syncthreads();
    }

    // epilogue
#pragma unroll
    for (int mt = 0; mt < 4; mt++) {
        int co = co0 + mt * 16 + (lane >> 2);
        float bv0 = bias[co];
        float bv1 = bias[co + 8];
        float* o0 = out + ((size_t)(b * CO + co) * DOUT + l) * HW + p0 + p0l;
        float* o1 = o0 + (size_t)8 * DOUT * HW;
#pragma unroll
        for (int nt = 0; nt < 4; nt++) {
            int p = nt * 8 + (lane & 3) * 2;
            float2 v0, v1;
            v0.x = (acc[mt][nt][0] + bv0) * scale;
            v0.y = (acc[mt][nt][1] + bv0) * scale;
            v1.x = (acc[mt][nt][2] + bv1) * scale;
            v1.y = (acc[mt][nt][3] + bv1) * scale;
            *(float2*)(o0 + p) = v0;
            *(float2*)(o1 + p) = v1;
        }
    }
}

// ---------------- attention stages (fp32 FFMA) -----------------------------
__global__ __launch_bounds__(256) void logits_k() {
    const int lchunk = blockIdx.x, bn = blockIdx.y;
    const int b = bn >> 1, n = bn & 1;
    const int l = n * 9 + lchunk;
    const float* Qb = g_Q + ((size_t)b * CO * LL + l) * HW;
    const float* Kb = g_K + ((size_t)b * CO * LL + l) * HW;
    __shared__ float Qs[32][129];
    __shared__ float Ks[32][129];
    const int tid = threadIdx.x;
    const int ty = tid >> 4, tx = tid & 15;
    float acc[8][8];
#pragma unroll
    for (int i = 0; i < 8; i++)
#pragma unroll
        for (int j = 0; j < 8; j++) acc[i][j] = 0.f;

    for (int hw0 = 0; hw0 < HW; hw0 += 32) {
#pragma unroll
        for (int i = 0; i < 16; i++) {
            int idx = tid + i * 256;
            int c = idx >> 5, kk = idx & 31;
            Qs[kk][c] = Qb[(size_t)c * LL * HW + hw0 + kk];
            Ks[kk][c] = Kb[(size_t)c * LL * HW + hw0 + kk];
        }
        __syncthreads();
#pragma unroll
        for (int kk = 0; kk < 32; kk++) {
            float a[8], bb[8];
#pragma unroll
            for (int i = 0; i < 8; i++) a[i] = Qs[kk][ty * 8 + i];
#pragma unroll
            for (int j = 0; j < 8; j++) bb[j] = Ks[kk][tx * 8 + j];
#pragma unroll
            for (int i = 0; i < 8; i++)
#pragma unroll
                for (int j = 0; j < 8; j++) acc[i][j] += a[i] * bb[j];
        }
        __syncthreads();
    }
    float* lp = g_lp + ((size_t)lchunk * 16 + bn) * CO * CO;
#pragma unroll
    for (int i = 0; i < 8; i++) {
        int c = ty * 8 + i;
#pragma unroll
        for (int j = 0; j < 8; j++) lp[(size_t)c * CO + tx * 8 + j] = acc[i][j];
    }
}

__global__ __launch_bounds__(256) void softmax_k() {
    const int warp = (blockIdx.x * 256 + threadIdx.x) >> 5;
    const int lane = threadIdx.x & 31;
    if (warp >= 16 * CO) return;
    const int bn = warp >> 7, c = warp & 127;
    float v[4];
#pragma unroll
    for (int j = 0; j < 4; j++) {
        int m = lane + j * 32;
        float s = 0.f;
#pragma unroll
        for (int p = 0; p < 9; p++)
            s += g_lp[(((size_t)p * 16 + bn) * CO + c) * CO + m];
        v[j] = s;
    }
    float mx = fmaxf(fmaxf(v[0], v[1]), fmaxf(v[2], v[3]));
#pragma unroll
    for (int o = 16; o; o >>= 1) mx = fmaxf(mx, __shfl_xor_sync(0xffffffffu, mx, o));
    float sum = 0.f;
#pragma unroll
    for (int j = 0; j < 4; j++) { v[j] = __expf(v[j] - mx); sum += v[j]; }
#pragma unroll
    for (int o = 16; o; o >>= 1) sum += __shfl_xor_sync(0xffffffffu, sum, o);
    float inv = 1.f / sum;
#pragma unroll
    for (int j = 0; j < 4; j++)
        g_attn[((size_t)bn * CO + c) * CO + lane + j * 32] = v[j] * inv;
}

__global__ __launch_bounds__(256) void out_k(float* __restrict__ out) {
    const int p0 = blockIdx.x * 128;
    const int s = blockIdx.y;
    const int b = s >> 4, l = s & 15, n = l >> 3;
    const float* A = g_attn + (size_t)(b * 2 + n) * CO * CO;
    __shared__ float As[32][129];
    __shared__ float Bs[32][128];
    const int tid = threadIdx.x;
    const int ty = tid >> 4, tx = tid & 15;
    float acc[8][8];
#pragma unroll
    for (int i = 0; i < 8; i++)
#pragma unroll
        for (int j = 0; j < 8; j++) acc[i][j] = 0.f;

    for (int m0 = 0; m0 < 128; m0 += 32) {
#pragma unroll
        for (int i = 0; i < 16; i++) {
            int idx = tid + i * 256;
            int c = idx >> 5, mm = idx & 31;
            As[mm][c] = A[(size_t)c * CO + m0 + mm];
        }
#pragma unroll
        for (int i = 0; i < 16; i++) {
            int idx = tid + i * 256;
            int mm = idx >> 7, p = idx & 127;
            Bs[mm][p] = g_V[((size_t)(b * CO + m0 + mm) * LV + l) * HW + p0 + p];
        }
        __syncthreads();
#pragma unroll
        for (int kk = 0; kk < 32; kk++) {
            float a[8], bb[8];
#pragma unroll
            for (int i = 0; i < 8; i++) a[i] = As[kk][ty * 8 + i];
#pragma unroll
            for (int j = 0; j < 8; j++) bb[j] = Bs[kk][tx * 8 + j];
#pragma unroll
            for (int i = 0; i < 8; i++)
#pragma unroll
                for (int j = 0; j < 8; j++) acc[i][j] += a[i] * bb[j];
        }
        __syncthreads();
    }
#pragma unroll
    for (int i = 0; i < 8; i++) {
        int c = ty * 8 + i;
        float* op = out + ((size_t)(b * CO + c) * LV + l) * HW + p0 + tx * 8;
#pragma unroll
        for (int j = 0; j < 8; j++) op[j] = acc[i][j];
    }
}

// ---------------------------------------------------------------------------
extern "C" void kernel_launch(void* const* d_in, const int* in_sizes, int n_in,
                              void* d_out, int out_size) {
    const float* input  = (const float*)d_in[0];
    const float* memory = (const float*)d_in[1];
    const float* wq = (const float*)d_in[2];
    const float* bq = (const float*)d_in[3];
    const float* wk = (const float*)d_in[4];
    const float* bk = (const float*)d_in[5];
    const float* wv = (const float*)d_in[6];
    const float* bv = (const float*)d_in[7];
    float* out = (float*)d_out;

    cudaFuncSetAttribute(convmma_k, cudaFuncAttributeMaxDynamicSharedMemorySize,
                         SMEMSZ);

    pack_k<<<dim3(BB * LL, 16), 256>>>(input, 0);
    pack_k<<<dim3(BB * LL, 16), 256>>>(memory, 1);
    wprep_k<<<(9 * 8192 + 255) / 256, 256>>>(wq, 9, 0);
    wprep_k<<<(9 * 8192 + 255) / 256, 256>>>(wk, 9, 1);
    wprep_k<<<(27 * 8192 + 255) / 256, 256>>>(wv, 27, 2);

    convmma_k<<<dim3(8, BB * LL), 256, SMEMSZ>>>(bq, 0, LL, 9, 0, 0.5f);
    convmma_k<<<dim3(8, BB * LL), 256, SMEMSZ>>>(bk, 1, LL, 9, 0, 1.0f);
    convmma_k<<<dim3(8, BB * LV), 256, SMEMSZ>>>(bv, 2, LV, 27, 1, 1.0f);

    logits_k<<<dim3(9, 16), 256>>>();
    softmax_k<<<256, 256>>>();
    out_k<<<dim3(8, BB * LV), 256>>>(out);
}

// round 4
// speedup vs baseline: 3.5635x; 1.1627x over previous
#include <cuda_runtime.h>
#include <cuda_bf16.h>
#include <cstdint>

#define BB   8
#define CIN  64
#define CO   128
#define LL   18
#define LV   16
#define HW   1024
#define NH   2

// ---------------- scratch (device globals; no allocation allowed) ----------
__device__ float g_lp[(size_t)9*BB*NH*CO*CO];

// split bf16 Q/K planes [b][c][l=18][hw], V planes [b][m][l=16][hw]
__device__ __nv_bfloat16 g_Qh[(size_t)BB*CO*LL*HW];
__device__ __nv_bfloat16 g_Ql[(size_t)BB*CO*LL*HW];
__device__ __nv_bfloat16 g_Kh[(size_t)BB*CO*LL*HW];
__device__ __nv_bfloat16 g_Kl[(size_t)BB*CO*LL*HW];
__device__ __nv_bfloat16 g_Vh[(size_t)BB*CO*LV*HW];
__device__ __nv_bfloat16 g_Vl[(size_t)BB*CO*LV*HW];
// split bf16 attn [bn][c][m]
__device__ __nv_bfloat16 g_aH[(size_t)BB*NH*CO*CO];
__device__ __nv_bfloat16 g_aL[(size_t)BB*NH*CO*CO];

// transposed split-bf16 inputs: [b][l][hw][ci]
__device__ __nv_bfloat16 g_hin[(size_t)BB*LL*HW*CIN];
__device__ __nv_bfloat16 g_lin[(size_t)BB*LL*HW*CIN];
__device__ __nv_bfloat16 g_hmm[(size_t)BB*LL*HW*CIN];
__device__ __nv_bfloat16 g_lmm[(size_t)BB*LL*HW*CIN];
// weight tile images, pitch 72 halves: [chunk][co=128][72]
__device__ uint4 g_wqh[9*1152],  g_wql[9*1152];
__device__ uint4 g_wkh[9*1152],  g_wkl[9*1152];
__device__ uint4 g_wvh[27*1152], g_wvl[27*1152];

// ---------------- PTX helpers ----------------------------------------------
__device__ __forceinline__ uint32_t smem_u32(const void* p) {
    uint32_t a;
    asm("{ .reg .u64 t; cvta.to.shared.u64 t, %1; cvt.u32.u64 %0, t; }"
        : "=r"(a) : "l"(p));
    return a;
}
__device__ __forceinline__ void ldmat4(uint32_t& r0, uint32_t& r1, uint32_t& r2,
                                       uint32_t& r3, uint32_t a) {
    asm volatile("ldmatrix.sync.aligned.m8n8.x4.shared.b16 {%0,%1,%2,%3}, [%4];"
                 : "=r"(r0), "=r"(r1), "=r"(r2), "=r"(r3) : "r"(a));
}
__device__ __forceinline__ void ldmat2(uint32_t& r0, uint32_t& r1, uint32_t a) {
    asm volatile("ldmatrix.sync.aligned.m8n8.x2.shared.b16 {%0,%1}, [%2];"
                 : "=r"(r0), "=r"(r1) : "r"(a));
}
__device__ __forceinline__ void ldmat2t(uint32_t& r0, uint32_t& r1, uint32_t a) {
    asm volatile("ldmatrix.sync.aligned.m8n8.x2.trans.shared.b16 {%0,%1}, [%2];"
                 : "=r"(r0), "=r"(r1) : "r"(a));
}
__device__ __forceinline__ void mma16816(float* c, const uint32_t* a,
                                         const uint32_t* b) {
    asm volatile(
        "mma.sync.aligned.m16n8k16.row.col.f32.bf16.bf16.f32 "
        "{%0,%1,%2,%3}, {%4,%5,%6,%7}, {%8,%9}, {%0,%1,%2,%3};"
        : "+f"(c[0]), "+f"(c[1]), "+f"(c[2]), "+f"(c[3])
        : "r"(a[0]), "r"(a[1]), "r"(a[2]), "r"(a[3]), "r"(b[0]), "r"(b[1]));
}
__device__ __forceinline__ void cpasync16(uint32_t dst, const void* src, int sz) {
    asm volatile("cp.async.ca.shared.global [%0], [%1], 16, %2;"
                 :: "r"(dst), "l"(src), "r"(sz) : "memory");
}
__device__ __forceinline__ void cp_commit() {
    asm volatile("cp.async.commit_group;" ::: "memory");
}
__device__ __forceinline__ void cp_wait1() {
    asm volatile("cp.async.wait_group 1;" ::: "memory");
}
__device__ __forceinline__ void cp_wait0() {
    asm volatile("cp.async.wait_group 0;" ::: "memory");
}

__device__ __forceinline__ void emit_split(__nv_bfloat16* ph, __nv_bfloat16* pl,
                                           float x, float y) {
    __nv_bfloat162 h, l;
    h.x = __float2bfloat16(x);
    h.y = __float2bfloat16(y);
    l.x = __float2bfloat16(x - __bfloat162float(h.x));
    l.y = __float2bfloat16(y - __bfloat162float(h.y));
    *(__nv_bfloat162*)ph = h;
    *(__nv_bfloat162*)pl = l;
}

// ---------------- prep kernels ---------------------------------------------
__global__ __launch_bounds__(256) void pack_k(const float* __restrict__ x, int dst) {
    __shared__ float tile[64][65];
    const int s = blockIdx.x;
    const int hw0 = blockIdx.y * 64;
    const int b = s / LL, l = s % LL;
    __nv_bfloat16* oh = dst ? g_hmm : g_hin;
    __nv_bfloat16* ol = dst ? g_lmm : g_lin;
#pragma unroll
    for (int i = 0; i < 16; i++) {
        int idx = threadIdx.x + i * 256;
        int ci = idx >> 6, hw = idx & 63;
        tile[ci][hw] = x[(((size_t)b * CIN + ci) * LL + l) * HW + hw0 + hw];
    }
    __syncthreads();
#pragma unroll
    for (int i = 0; i < 16; i++) {
        int idx = threadIdx.x + i * 256;
        int hw = idx >> 6, ci = idx & 63;
        float v = tile[ci][hw];
        __nv_bfloat16 h = __float2bfloat16(v);
        size_t o = ((size_t)s * HW + hw0 + hw) * CIN + ci;
        oh[o] = h;
        ol[o] = __float2bfloat16(v - __bfloat162float(h));
    }
}

__global__ __launch_bounds__(256) void wprep_k(const float* __restrict__ w,
                                               int nchunk, int dst) {
    int i = blockIdx.x * 256 + threadIdx.x;
    if (i >= nchunk * 8192) return;
    int c = i >> 13, r = i & 8191, co = r >> 6, ci = r & 63;
    float v = w[(co * 64 + ci) * nchunk + c];
    __nv_bfloat16 h = __float2bfloat16(v);
    __nv_bfloat16 lo = __float2bfloat16(v - __bfloat162float(h));
    __nv_bfloat16 *oh, *ol;
    if (dst == 0)      { oh = (__nv_bfloat16*)g_wqh; ol = (__nv_bfloat16*)g_wql; }
    else if (dst == 1) { oh = (__nv_bfloat16*)g_wkh; ol = (__nv_bfloat16*)g_wkl; }
    else               { oh = (__nv_bfloat16*)g_wvh; ol = (__nv_bfloat16*)g_wvl; }
    oh[(size_t)c * 9216 + co * 72 + ci] = h;
    ol[(size_t)c * 9216 + co * 72 + ci] = lo;
}

// ---------------- HMMA implicit-GEMM conv ----------------------------------
#define ABYTES 18432
#define BUFSZ  73728
#define SMEMSZ (2*BUFSZ)

__device__ __forceinline__ void issue_chunk(
    int c, int is3d, int p0, int b, int l, uint32_t sb,
    const uint4* wh, const uint4* wl,
    const __nv_bfloat16* xh, const __nv_bfloat16* xl, int tid) {
    int kd, kh, kw;
    if (is3d) { kd = c / 9; int r = c % 9; kh = r / 3; kw = r % 3; }
    else      { kd = 0; kh = c / 3; kw = c % 3; }
    const uint32_t base = sb + (c & 1) * BUFSZ;
#pragma unroll
    for (int i = 0; i < 9; i++) {
        int idx = tid + i * 256;
        if (idx < 2304) {
            int half = idx >= 1152;
            int r = idx - half * 1152;
            const uint4* s = (half ? wl : wh) + (size_t)c * 1152 + r;
            cpasync16(base + half * ABYTES + r * 16, s, 16);
        }
    }
    {
        int row = tid >> 1, sub = tid & 1;
        int pg = p0 + row;
        int ih = (pg >> 5) + kh - 1, iw = (pg & 31) + kw - 1;
        int ok = ((unsigned)ih < 32u) && ((unsigned)iw < 32u);
        int ihc = ok ? ih : 0, iwc = ok ? iw : 0;
        const __nv_bfloat16* s = (sub ? xl : xh) +
            ((size_t)((b * LL + l + kd) * HW) + ihc * 32 + iwc) * CIN;
        uint32_t dst = base + 36864 + sub * ABYTES + row * 144;
        int sz = ok ? 16 : 0;
#pragma unroll
        for (int j = 0; j < 8; j++)
            cpasync16(dst + j * 16, (const char*)s + j * 16, sz);
    }
    cp_commit();
}

__global__ __launch_bounds__(256, 1)
void convmma_k(const float* __restrict__ bias, int mode, int DOUT, int NC,
               int is3d, float scale) {
    extern __shared__ char smem[];
    const uint32_t sb = smem_u32(smem);
    const int tid = threadIdx.x, wid = tid >> 5, lane = tid & 31;
    const int p0 = blockIdx.x * 128;
    const int b = blockIdx.y / DOUT, l = blockIdx.y % DOUT;

    const __nv_bfloat16 *xh, *xl;
    const uint4 *wh, *wl;
    __nv_bfloat16 *oph, *opl;
    if (mode == 0)      { xh = g_hin; xl = g_lin; wh = g_wqh; wl = g_wql;
                          oph = g_Qh; opl = g_Ql; }
    else if (mode == 1) { xh = g_hmm; xl = g_lmm; wh = g_wkh; wl = g_wkl;
                          oph = g_Kh; opl = g_Kl; }
    else                { xh = g_hmm; xl = g_lmm; wh = g_wvh; wl = g_wvl;
                          oph = g_Vh; opl = g_Vl; }

    const int co0 = (wid & 1) * 64;
    const int p0l = (wid >> 1) * 32;

    float acc[4][4][4];
#pragma unroll
    for (int mt = 0; mt < 4; mt++)
#pragma unroll
        for (int nt = 0; nt < 4; nt++)
#pragma unroll
            for (int i = 0; i < 4; i++) acc[mt][nt][i] = 0.f;

    issue_chunk(0, is3d, p0, b, l, sb, wh, wl, xh, xl, tid);

    for (int c = 0; c < NC; c++) {
        if (c + 1 < NC) {
            issue_chunk(c + 1, is3d, p0, b, l, sb, wh, wl, xh, xl, tid);
            cp_wait1();
        } else {
            cp_wait0();
        }
        __syncthreads();
        const uint32_t base = sb + (c & 1) * BUFSZ;
        const uint32_t aAh = base, aAl = base + ABYTES;
        const uint32_t aBh = base + 36864, aBl = base + 36864 + ABYTES;
#pragma unroll
        for (int k = 0; k < 4; k++) {
            uint32_t ah[4][4], al[4][4], bh[4][2], bl[4][2];
#pragma unroll
            for (int mt = 0; mt < 4; mt++) {
                uint32_t off = (uint32_t)(((co0 + mt * 16 + (lane & 15)) * 72 +
                                           k * 16 + (lane >> 4) * 8) * 2);
                ldmat4(ah[mt][0], ah[mt][1], ah[mt][2], ah[mt][3], aAh + off);
                ldmat4(al[mt][0], al[mt][1], al[mt][2], al[mt][3], aAl + off);
            }
#pragma unroll
            for (int nt = 0; nt < 4; nt++) {
                uint32_t off = (uint32_t)(((p0l + nt * 8 + (lane & 7)) * 72 +
                                           k * 16 + ((lane >> 3) & 1) * 8) * 2);
                ldmat2(bh[nt][0], bh[nt][1], aBh + off);
                ldmat2(bl[nt][0], bl[nt][1], aBl + off);
            }
#pragma unroll
            for (int mt = 0; mt < 4; mt++)
#pragma unroll
                for (int nt = 0; nt < 4; nt++)
                    mma16816(acc[mt][nt], ah[mt], bh[nt]);
#pragma unroll
            for (int mt = 0; mt < 4; mt++)
#pragma unroll
                for (int nt = 0; nt < 4; nt++)
                    mma16816(acc[mt][nt], ah[mt], bl[nt]);
#pragma unroll
            for (int mt = 0; mt < 4; mt++)
#pragma unroll
                for (int nt = 0; nt < 4; nt++)
                    mma16816(acc[mt][nt], al[mt], bh[nt]);
        }
        __syncthreads();
    }

    // epilogue: emit split bf16 hi/lo planes
#pragma unroll
    for (int mt = 0; mt < 4; mt++) {
        int co = co0 + mt * 16 + (lane >> 2);
        float bv0 = bias[co];
        float bv1 = bias[co + 8];
        size_t o0 = ((size_t)(b * CO + co) * DOUT + l) * HW + p0 + p0l;
        size_t o1 = o0 + (size_t)8 * DOUT * HW;
#pragma unroll
        for (int nt = 0; nt < 4; nt++) {
            int p = nt * 8 + (lane & 3) * 2;
            emit_split(oph + o0 + p, opl + o0 + p,
                       (acc[mt][nt][0] + bv0) * scale,
                       (acc[mt][nt][1] + bv0) * scale);
            emit_split(oph + o1 + p, opl + o1 + p,
                       (acc[mt][nt][2] + bv1) * scale,
                       (acc[mt][nt][3] + bv1) * scale);
        }
    }
}

// ---------------- logits: Q.K^T via HMMA, split-K over 9 l-slices ----------
__global__ __launch_bounds__(256, 1) void logits2_k() {
    extern __shared__ char smem[];
    const uint32_t sb = smem_u32(smem);
    const int tid = threadIdx.x, wid = tid >> 5, lane = tid & 31;
    const int lc = blockIdx.x, bn = blockIdx.y;
    const int b = bn >> 1, n = bn & 1;
    const int l = n * 9 + lc;

    const __nv_bfloat16* srcs[4];
    srcs[0] = g_Qh + ((size_t)(b * CO) * LL + l) * HW;
    srcs[1] = g_Ql + ((size_t)(b * CO) * LL + l) * HW;
    srcs[2] = g_Kh + ((size_t)(b * CO) * LL + l) * HW;
    srcs[3] = g_Kl + ((size_t)(b * CO) * LL + l) * HW;

    const int co0 = (wid & 1) * 64;   // q channel rows
    const int p0l = (wid >> 1) * 32;  // k channel cols

    float acc[4][4][4];
#pragma unroll
    for (int mt = 0; mt < 4; mt++)
#pragma unroll
        for (int nt = 0; nt < 4; nt++)
#pragma unroll
            for (int i = 0; i < 4; i++) acc[mt][nt][i] = 0.f;

    // issue chunk: 4 planes x 128 rows x 128B into pitch-144 tiles
    auto issue = [&](int ch) {
        const uint32_t base = sb + (ch & 1) * BUFSZ;
        const int hw0 = ch * 64;
#pragma unroll
        for (int r = tid; r < 512; r += 256) {
            int plane = r >> 7, c = r & 127;
            const __nv_bfloat16* s = srcs[plane] + (size_t)c * (LL * HW) + hw0;
            uint32_t dst = base + plane * ABYTES + c * 144;
#pragma unroll
            for (int j = 0; j < 8; j++)
                cpasync16(dst + j * 16, (const char*)s + j * 16, 16);
        }
        cp_commit();
    };

    issue(0);
    for (int ch = 0; ch < 16; ch++) {
        if (ch + 1 < 16) { issue(ch + 1); cp_wait1(); }
        else             { cp_wait0(); }
        __syncthreads();
        const uint32_t base = sb + (ch & 1) * BUFSZ;
        const uint32_t aAh = base, aAl = base + ABYTES;
        const uint32_t aBh = base + 2 * ABYTES, aBl = base + 3 * ABYTES;
#pragma unroll
        for (int k = 0; k < 4; k++) {
            uint32_t ah[4][4], al[4][4], bh[4][2], bl[4][2];
#pragma unroll
            for (int mt = 0; mt < 4; mt++) {
                uint32_t off = (uint32_t)(((co0 + mt * 16 + (lane & 15)) * 72 +
                                           k * 16 + (lane >> 4) * 8) * 2);
                ldmat4(ah[mt][0], ah[mt][1], ah[mt][2], ah[mt][3], aAh + off);
                ldmat4(al[mt][0], al[mt][1], al[mt][2], al[mt][3], aAl + off);
            }
#pragma unroll
            for (int nt = 0; nt < 4; nt++) {
                uint32_t off = (uint32_t)(((p0l + nt * 8 + (lane & 7)) * 72 +
                                           k * 16 + ((lane >> 3) & 1) * 8) * 2);
                ldmat2(bh[nt][0], bh[nt][1], aBh + off);
                ldmat2(bl[nt][0], bl[nt][1], aBl + off);
            }
#pragma unroll
            for (int mt = 0; mt < 4; mt++)
#pragma unroll
                for (int nt = 0; nt < 4; nt++)
                    mma16816(acc[mt][nt], ah[mt], bh[nt]);
#pragma unroll
            for (int mt = 0; mt < 4; mt++)
#pragma unroll
                for (int nt = 0; nt < 4; nt++)
                    mma16816(acc[mt][nt], ah[mt], bl[nt]);
#pragma unroll
            for (int mt = 0; mt < 4; mt++)
#pragma unroll
                for (int nt = 0; nt < 4; nt++)
                    mma16816(acc[mt][nt], al[mt], bh[nt]);
        }
        __syncthreads();
    }

    float* lp = g_lp + ((size_t)lc * 16 + bn) * CO * CO;
#pragma unroll
    for (int mt = 0; mt < 4; mt++) {
        int c = co0 + mt * 16 + (lane >> 2);
#pragma unroll
        for (int nt = 0; nt < 4; nt++) {
            int m = p0l + nt * 8 + (lane & 3) * 2;
            *(float2*)(lp + (size_t)c * CO + m) =
                make_float2(acc[mt][nt][0], acc[mt][nt][1]);
            *(float2*)(lp + (size_t)(c + 8) * CO + m) =
                make_float2(acc[mt][nt][2], acc[mt][nt][3]);
        }
    }
}

// ---------------- softmax: reduce partials, emit split bf16 attn -----------
__global__ __launch_bounds__(256) void softmax_k() {
    const int warp = (blockIdx.x * 256 + threadIdx.x) >> 5;
    const int lane = threadIdx.x & 31;
    if (warp >= 16 * CO) return;
    const int bn = warp >> 7, c = warp & 127;
    float v[4];
#pragma unroll
    for (int j = 0; j < 4; j++) {
        int m = lane + j * 32;
        float s = 0.f;
#pragma unroll
        for (int p = 0; p < 9; p++)
            s += g_lp[(((size_t)p * 16 + bn) * CO + c) * CO + m];
        v[j] = s;
    }
    float mx = fmaxf(fmaxf(v[0], v[1]), fmaxf(v[2], v[3]));
#pragma unroll
    for (int o = 16; o; o >>= 1) mx = fmaxf(mx, __shfl_xor_sync(0xffffffffu, mx, o));
    float sum = 0.f;
#pragma unroll
    for (int j = 0; j < 4; j++) { v[j] = __expf(v[j] - mx); sum += v[j]; }
#pragma unroll
    for (int o = 16; o; o >>= 1) sum += __shfl_xor_sync(0xffffffffu, sum, o);
    float inv = 1.f / sum;
#pragma unroll
    for (int j = 0; j < 4; j++) {
        float a = v[j] * inv;
        __nv_bfloat16 h = __float2bfloat16(a);
        size_t o = ((size_t)bn * CO + c) * CO + lane + j * 32;
        g_aH[o] = h;
        g_aL[o] = __float2bfloat16(a - __bfloat162float(h));
    }
}

// ---------------- out: attn x V via HMMA -----------------------------------
// A = attn[c][m] row-major; B = V[m][pix] -> ldmatrix.trans for [pix][m] frags
#define OPITCH 272
#define OTILE  34816   // 128*272
#define OSMEM  (4*OTILE)

__global__ __launch_bounds__(256, 1) void out2_k(float* __restrict__ out) {
    extern __shared__ char smem[];
    const uint32_t sb = smem_u32(smem);
    const int tid = threadIdx.x, wid = tid >> 5, lane = tid & 31;
    const int pt = blockIdx.x, b = blockIdx.y;
    const int l = pt >> 3;
    const int hw0 = (pt & 7) * 128;
    const int bn = b * 2 + (l >> 3);

    // load attn tiles (hi/lo) and V tiles (hi/lo)
    {
        int plane = tid >> 7, c = tid & 127;
        const __nv_bfloat16* s =
            (plane ? g_aL : g_aH) + ((size_t)bn * CO + c) * CO;
        uint32_t dst = sb + plane * OTILE + c * OPITCH;
#pragma unroll
        for (int j = 0; j < 16; j++)
            cpasync16(dst + j * 16, (const char*)s + j * 16, 16);
        const __nv_bfloat16* sv =
            (plane ? g_Vl : g_Vh) + ((size_t)(b * CO + c) * LV + l) * HW + hw0;
        uint32_t dv = sb + 2 * OTILE + plane * OTILE + c * OPITCH;
#pragma unroll
        for (int j = 0; j < 16; j++)
            cpasync16(dv + j * 16, (const char*)sv + j * 16, 16);
    }
    cp_commit();
    cp_wait0();
    __syncthreads();

    const int co0 = (wid & 1) * 64;   // out channel rows
    const int p0l = (wid >> 1) * 32;  // pixel cols
    const uint32_t aAh = sb, aAl = sb + OTILE;
    const uint32_t aBh = sb + 2 * OTILE, aBl = sb + 3 * OTILE;

    float acc[4][4][4];
#pragma unroll
    for (int mt = 0; mt < 4; mt++)
#pragma unroll
        for (int nt = 0; nt < 4; nt++)
#pragma unroll
            for (int i = 0; i < 4; i++) acc[mt][nt][i] = 0.f;

#pragma unroll
    for (int kc = 0; kc < 8; kc++) {
        uint32_t ah[4][4], al[4][4], bh[4][2], bl[4][2];
#pragma unroll
        for (int mt = 0; mt < 4; mt++) {
            uint32_t off = (uint32_t)((co0 + mt * 16 + (lane & 15)) * OPITCH +
                                      kc * 32 + (lane >> 4) * 16);
            ldmat4(ah[mt][0], ah[mt][1], ah[mt][2], ah[mt][3], aAh + off);
            ldmat4(al[mt][0], al[mt][1], al[mt][2], al[mt][3], aAl + off);
        }
#pragma unroll
        for (int nt = 0; nt < 4; nt++) {
            uint32_t off = (uint32_t)((kc * 16 + (lane & 15)) * OPITCH +
                                      (p0l + nt * 8) * 2);
            ldmat2t(bh[nt][0], bh[nt][1], aBh + off);
            ldmat2t(bl[nt][0], bl[nt][1], aBl + off);
        }
#pragma unroll
        for (int mt = 0; mt < 4; mt++)
#pragma unroll
            for (int nt = 0; nt < 4; nt++)
                mma16816(acc[mt][nt], ah[mt], bh[nt]);
#pragma unroll
        for (int mt = 0; mt < 4; mt++)
#pragma unroll
            for (int nt = 0; nt < 4; nt++)
                mma16816(acc[mt][nt], ah[mt], bl[nt]);
#pragma unroll
        for (int mt = 0; mt < 4; mt++)
#pragma unroll
            for (int nt = 0; nt < 4; nt++)
                mma16816(acc[mt][nt], al[mt], bh[nt]);
    }

#pragma unroll
    for (int mt = 0; mt < 4; mt++) {
        int c = co0 + mt * 16 + (lane >> 2);
        float* o0 = out + ((size_t)(b * CO + c) * LV + l) * HW + hw0 + p0l;
        float* o1 = o0 + (size_t)8 * LV * HW;
#pragma unroll
        for (int nt = 0; nt < 4; nt++) {
            int p = nt * 8 + (lane & 3) * 2;
            *(float2*)(o0 + p) = make_float2(acc[mt][nt][0], acc[mt][nt][1]);
            *(float2*)(o1 + p) = make_float2(acc[mt][nt][2], acc[mt][nt][3]);
        }
    }
}

// ---------------------------------------------------------------------------
extern "C" void kernel_launch(void* const* d_in, const int* in_sizes, int n_in,
                              void* d_out, int out_size) {
    const float* input  = (const float*)d_in[0];
    const float* memory = (const float*)d_in[1];
    const float* wq = (const float*)d_in[2];
    const float* bq = (const float*)d_in[3];
    const float* wk = (const float*)d_in[4];
    const float* bk = (const float*)d_in[5];
    const float* wv = (const float*)d_in[6];
    const float* bv = (const float*)d_in[7];
    float* out = (float*)d_out;

    cudaFuncSetAttribute(convmma_k, cudaFuncAttributeMaxDynamicSharedMemorySize,
                         SMEMSZ);
    cudaFuncSetAttribute(logits2_k, cudaFuncAttributeMaxDynamicSharedMemorySize,
                         SMEMSZ);
    cudaFuncSetAttribute(out2_k, cudaFuncAttributeMaxDynamicSharedMemorySize,
                         OSMEM);

    pack_k<<<dim3(BB * LL, 16), 256>>>(input, 0);
    pack_k<<<dim3(BB * LL, 16), 256>>>(memory, 1);
    wprep_k<<<(9 * 8192 + 255) / 256, 256>>>(wq, 9, 0);
    wprep_k<<<(9 * 8192 + 255) / 256, 256>>>(wk, 9, 1);
    wprep_k<<<(27 * 8192 + 255) / 256, 256>>>(wv, 27, 2);

    convmma_k<<<dim3(8, BB * LL), 256, SMEMSZ>>>(bq, 0, LL, 9, 0, 0.5f);
    convmma_k<<<dim3(8, BB * LL), 256, SMEMSZ>>>(bk, 1, LL, 9, 0, 1.0f);
    convmma_k<<<dim3(8, BB * LV), 256, SMEMSZ>>>(bv, 2, LV, 27, 1, 1.0f);

    logits2_k<<<dim3(9, 16), 256, SMEMSZ>>>();
    softmax_k<<<256, 256>>>();
    out2_k<<<dim3(128, 8), 256, OSMEM>>>(out);
}

// round 5
// speedup vs baseline: 3.8990x; 1.0942x over previous
#include <cuda_runtime.h>
#include <cuda_fp16.h>
#include <cstdint>

#define BB   8
#define CIN  64
#define CO   128
#define LL   18
#define LV   16
#define HW   1024
#define NH   2

// ---------------- scratch (device globals; no allocation allowed) ----------
__device__ float g_lp[(size_t)9*BB*NH*CO*CO];

// split fp16 Q/K planes [b][c][l=18][hw], V planes [b][m][l=16][hw]
__device__ __half g_Qh[(size_t)BB*CO*LL*HW];
__device__ __half g_Ql[(size_t)BB*CO*LL*HW];
__device__ __half g_Kh[(size_t)BB*CO*LL*HW];
__device__ __half g_Kl[(size_t)BB*CO*LL*HW];
__device__ __half g_Vh[(size_t)BB*CO*LV*HW];
__device__ __half g_Vl[(size_t)BB*CO*LV*HW];
// split fp16 attn [bn][c][m]
__device__ __half g_aH[(size_t)BB*NH*CO*CO];
__device__ __half g_aL[(size_t)BB*NH*CO*CO];

// transposed split-fp16 inputs: [b][l][hw][ci]
__device__ __half g_hin[(size_t)BB*LL*HW*CIN];
__device__ __half g_lin[(size_t)BB*LL*HW*CIN];
__device__ __half g_hmm[(size_t)BB*LL*HW*CIN];
__device__ __half g_lmm[(size_t)BB*LL*HW*CIN];
// weight tile images, pitch 72 halves: [chunk][co=128][72]
__device__ uint4 g_wqh[9*1152],  g_wql[9*1152];
__device__ uint4 g_wkh[9*1152],  g_wkl[9*1152];
__device__ uint4 g_wvh[27*1152], g_wvl[27*1152];

// ---------------- PTX helpers ----------------------------------------------
__device__ __forceinline__ uint32_t smem_u32(const void* p) {
    uint32_t a;
    asm("{ .reg .u64 t; cvta.to.shared.u64 t, %1; cvt.u32.u64 %0, t; }"
        : "=r"(a) : "l"(p));
    return a;
}
__device__ __forceinline__ void ldmat4(uint32_t& r0, uint32_t& r1, uint32_t& r2,
                                       uint32_t& r3, uint32_t a) {
    asm volatile("ldmatrix.sync.aligned.m8n8.x4.shared.b16 {%0,%1,%2,%3}, [%4];"
                 : "=r"(r0), "=r"(r1), "=r"(r2), "=r"(r3) : "r"(a));
}
__device__ __forceinline__ void ldmat2(uint32_t& r0, uint32_t& r1, uint32_t a) {
    asm volatile("ldmatrix.sync.aligned.m8n8.x2.shared.b16 {%0,%1}, [%2];"
                 : "=r"(r0), "=r"(r1) : "r"(a));
}
__device__ __forceinline__ void ldmat2t(uint32_t& r0, uint32_t& r1, uint32_t a) {
    asm volatile("ldmatrix.sync.aligned.m8n8.x2.trans.shared.b16 {%0,%1}, [%2];"
                 : "=r"(r0), "=r"(r1) : "r"(a));
}
__device__ __forceinline__ void mma16816(float* c, const uint32_t* a,
                                         const uint32_t* b) {
    asm volatile(
        "mma.sync.aligned.m16n8k16.row.col.f32.f16.f16.f32 "
        "{%0,%1,%2,%3}, {%4,%5,%6,%7}, {%8,%9}, {%0,%1,%2,%3};"
        : "+f"(c[0]), "+f"(c[1]), "+f"(c[2]), "+f"(c[3])
        : "r"(a[0]), "r"(a[1]), "r"(a[2]), "r"(a[3]), "r"(b[0]), "r"(b[1]));
}
__device__ __forceinline__ void cpasync16(uint32_t dst, const void* src, int sz) {
    asm volatile("cp.async.ca.shared.global [%0], [%1], 16, %2;"
                 :: "r"(dst), "l"(src), "r"(sz) : "memory");
}
__device__ __forceinline__ void cp_commit() {
    asm volatile("cp.async.commit_group;" ::: "memory");
}
__device__ __forceinline__ void cp_wait1() {
    asm volatile("cp.async.wait_group 1;" ::: "memory");
}
__device__ __forceinline__ void cp_wait0() {
    asm volatile("cp.async.wait_group 0;" ::: "memory");
}

__device__ __forceinline__ void emit_split(__half* ph, __half* pl,
                                           float x, float y) {
    __half2 h, l;
    h.x = __float2half_rn(x);
    h.y = __float2half_rn(y);
    l.x = __float2half_rn(x - __half2float(h.x));
    l.y = __float2half_rn(y - __half2float(h.y));
    *(__half2*)ph = h;
    *(__half2*)pl = l;
}

// ---------------- prep kernels ---------------------------------------------
__global__ __launch_bounds__(256) void pack_k(const float* __restrict__ x, int dst) {
    __shared__ float tile[64][65];
    const int s = blockIdx.x;
    const int hw0 = blockIdx.y * 64;
    const int b = s / LL, l = s % LL;
    __half* oh = dst ? g_hmm : g_hin;
    __half* ol = dst ? g_lmm : g_lin;
#pragma unroll
    for (int i = 0; i < 16; i++) {
        int idx = threadIdx.x + i * 256;
        int ci = idx >> 6, hw = idx & 63;
        tile[ci][hw] = x[(((size_t)b * CIN + ci) * LL + l) * HW + hw0 + hw];
    }
    __syncthreads();
#pragma unroll
    for (int i = 0; i < 16; i++) {
        int idx = threadIdx.x + i * 256;
        int hw = idx >> 6, ci = idx & 63;
        float v = tile[ci][hw];
        __half h = __float2half_rn(v);
        size_t o = ((size_t)s * HW + hw0 + hw) * CIN + ci;
        oh[o] = h;
        ol[o] = __float2half_rn(v - __half2float(h));
    }
}

__global__ __launch_bounds__(256) void wprep_k(const float* __restrict__ w,
                                               int nchunk, int dst) {
    int i = blockIdx.x * 256 + threadIdx.x;
    if (i >= nchunk * 8192) return;
    int c = i >> 13, r = i & 8191, co = r >> 6, ci = r & 63;
    float v = w[(co * 64 + ci) * nchunk + c];
    __half h = __float2half_rn(v);
    __half lo = __float2half_rn(v - __half2float(h));
    __half *oh, *ol;
    if (dst == 0)      { oh = (__half*)g_wqh; ol = (__half*)g_wql; }
    else if (dst == 1) { oh = (__half*)g_wkh; ol = (__half*)g_wkl; }
    else               { oh = (__half*)g_wvh; ol = (__half*)g_wvl; }
    oh[(size_t)c * 9216 + co * 72 + ci] = h;
    ol[(size_t)c * 9216 + co * 72 + ci] = lo;
}

// ---------------- HMMA implicit-GEMM conv ----------------------------------
#define ABYTES 18432
#define BUFSZ  73728
#define SMEMSZ (2*BUFSZ)

template<int NPASS>
__device__ __forceinline__ void issue_chunk(
    int c, int is3d, int p0, int b, int l, uint32_t sb,
    const uint4* wh, const uint4* wl,
    const __half* xh, const __half* xl, int tid) {
    int kd, kh, kw;
    if (is3d) { kd = c / 9; int r = c % 9; kh = r / 3; kw = r % 3; }
    else      { kd = 0; kh = c / 3; kw = c % 3; }
    const uint32_t base = sb + (c & 1) * BUFSZ;
    const int acop = (NPASS == 3) ? 2304 : 1152;
#pragma unroll
    for (int i = 0; i < 9; i++) {
        int idx = tid + i * 256;
        if (idx < acop) {
            int half_ = idx >= 1152;
            int r = idx - half_ * 1152;
            const uint4* s = (half_ ? wl : wh) + (size_t)c * 1152 + r;
            cpasync16(base + half_ * ABYTES + r * 16, s, 16);
        }
    }
    {
        int row = tid >> 1, sub = tid & 1;
        int pg = p0 + row;
        int ih = (pg >> 5) + kh - 1, iw = (pg & 31) + kw - 1;
        int ok = ((unsigned)ih < 32u) && ((unsigned)iw < 32u);
        int ihc = ok ? ih : 0, iwc = ok ? iw : 0;
        const __half* s = (sub ? xl : xh) +
            ((size_t)((b * LL + l + kd) * HW) + ihc * 32 + iwc) * CIN;
        uint32_t dst = base + 36864 + sub * ABYTES + row * 144;
        int sz = ok ? 16 : 0;
#pragma unroll
        for (int j = 0; j < 8; j++)
            cpasync16(dst + j * 16, (const char*)s + j * 16, sz);
    }
    cp_commit();
}

template<int NPASS>
__global__ __launch_bounds__(256, 1)
void convmma_k(const float* __restrict__ bias, int mode, int DOUT, int NC,
               int is3d, float scale) {
    extern __shared__ char smem[];
    const uint32_t sb = smem_u32(smem);
    const int tid = threadIdx.x, wid = tid >> 5, lane = tid & 31;
    const int p0 = blockIdx.x * 128;
    const int b = blockIdx.y / DOUT, l = blockIdx.y % DOUT;

    const __half *xh, *xl;
    const uint4 *wh, *wl;
    __half *oph, *opl;
    if (mode == 0)      { xh = g_hin; xl = g_lin; wh = g_wqh; wl = g_wql;
                          oph = g_Qh; opl = g_Ql; }
    else if (mode == 1) { xh = g_hmm; xl = g_lmm; wh = g_wkh; wl = g_wkl;
                          oph = g_Kh; opl = g_Kl; }
    else                { xh = g_hmm; xl = g_lmm; wh = g_wvh; wl = g_wvl;
                          oph = g_Vh; opl = g_Vl; }

    const int co0 = (wid & 1) * 64;
    const int p0l = (wid >> 1) * 32;

    float acc[4][4][4];
#pragma unroll
    for (int mt = 0; mt < 4; mt++)
#pragma unroll
        for (int nt = 0; nt < 4; nt++)
#pragma unroll
            for (int i = 0; i < 4; i++) acc[mt][nt][i] = 0.f;

    issue_chunk<NPASS>(0, is3d, p0, b, l, sb, wh, wl, xh, xl, tid);

    for (int c = 0; c < NC; c++) {
        if (c + 1 < NC) {
            issue_chunk<NPASS>(c + 1, is3d, p0, b, l, sb, wh, wl, xh, xl, tid);
            cp_wait1();
        } else {
            cp_wait0();
        }
        __syncthreads();
        const uint32_t base = sb + (c & 1) * BUFSZ;
        const uint32_t aAh = base, aAl = base + ABYTES;
        const uint32_t aBh = base + 36864, aBl = base + 36864 + ABYTES;
#pragma unroll
        for (int k = 0; k < 4; k++) {
            uint32_t ah[4][4], al[4][4], bh[4][2], bl[4][2];
#pragma unroll
            for (int mt = 0; mt < 4; mt++) {
                uint32_t off = (uint32_t)(((co0 + mt * 16 + (lane & 15)) * 72 +
                                           k * 16 + (lane >> 4) * 8) * 2);
                ldmat4(ah[mt][0], ah[mt][1], ah[mt][2], ah[mt][3], aAh + off);
                if (NPASS == 3)
                    ldmat4(al[mt][0], al[mt][1], al[mt][2], al[mt][3], aAl + off);
            }
#pragma unroll
            for (int nt = 0; nt < 4; nt++) {
                uint32_t off = (uint32_t)(((p0l + nt * 8 + (lane & 7)) * 72 +
                                           k * 16 + ((lane >> 3) & 1) * 8) * 2);
                ldmat2(bh[nt][0], bh[nt][1], aBh + off);
                ldmat2(bl[nt][0], bl[nt][1], aBl + off);
            }
#pragma unroll
            for (int mt = 0; mt < 4; mt++)
#pragma unroll
                for (int nt = 0; nt < 4; nt++)
                    mma16816(acc[mt][nt], ah[mt], bh[nt]);
#pragma unroll
            for (int mt = 0; mt < 4; mt++)
#pragma unroll
                for (int nt = 0; nt < 4; nt++)
                    mma16816(acc[mt][nt], ah[mt], bl[nt]);
            if (NPASS == 3) {
#pragma unroll
                for (int mt = 0; mt < 4; mt++)
#pragma unroll
                    for (int nt = 0; nt < 4; nt++)
                        mma16816(acc[mt][nt], al[mt], bh[nt]);
            }
        }
        __syncthreads();
    }

    // epilogue: emit split fp16 hi/lo planes
#pragma unroll
    for (int mt = 0; mt < 4; mt++) {
        int co = co0 + mt * 16 + (lane >> 2);
        float bv0 = bias[co];
        float bv1 = bias[co + 8];
        size_t o0 = ((size_t)(b * CO + co) * DOUT + l) * HW + p0 + p0l;
        size_t o1 = o0 + (size_t)8 * DOUT * HW;
#pragma unroll
        for (int nt = 0; nt < 4; nt++) {
            int p = nt * 8 + (lane & 3) * 2;
            emit_split(oph + o0 + p, opl + o0 + p,
                       (acc[mt][nt][0] + bv0) * scale,
                       (acc[mt][nt][1] + bv0) * scale);
            emit_split(oph + o1 + p, opl + o1 + p,
                       (acc[mt][nt][2] + bv1) * scale,
                       (acc[mt][nt][3] + bv1) * scale);
        }
    }
}

// ---------------- logits: Q.K^T via HMMA, split-K over 9 l-slices ----------
__global__ __launch_bounds__(256, 1) void logits2_k() {
    extern __shared__ char smem[];
    const uint32_t sb = smem_u32(smem);
    const int tid = threadIdx.x, wid = tid >> 5, lane = tid & 31;
    const int lc = blockIdx.x, bn = blockIdx.y;
    const int b = bn >> 1, n = bn & 1;
    const int l = n * 9 + lc;

    const __half* srcs[4];
    srcs[0] = g_Qh + ((size_t)(b * CO) * LL + l) * HW;
    srcs[1] = g_Ql + ((size_t)(b * CO) * LL + l) * HW;
    srcs[2] = g_Kh + ((size_t)(b * CO) * LL + l) * HW;
    srcs[3] = g_Kl + ((size_t)(b * CO) * LL + l) * HW;

    const int co0 = (wid & 1) * 64;
    const int p0l = (wid >> 1) * 32;

    float acc[4][4][4];
#pragma unroll
    for (int mt = 0; mt < 4; mt++)
#pragma unroll
        for (int nt = 0; nt < 4; nt++)
#pragma unroll
            for (int i = 0; i < 4; i++) acc[mt][nt][i] = 0.f;

    auto issue = [&](int ch) {
        const uint32_t base = sb + (ch & 1) * BUFSZ;
        const int hw0 = ch * 64;
#pragma unroll
        for (int r = tid; r < 512; r += 256) {
            int plane = r >> 7, c = r & 127;
            const __half* s = srcs[plane] + (size_t)c * (LL * HW) + hw0;
            uint32_t dst = base + plane * ABYTES + c * 144;
#pragma unroll
            for (int j = 0; j < 8; j++)
                cpasync16(dst + j * 16, (const char*)s + j * 16, 16);
        }
        cp_commit();
    };

    issue(0);
    for (int ch = 0; ch < 16; ch++) {
        if (ch + 1 < 16) { issue(ch + 1); cp_wait1(); }
        else             { cp_wait0(); }
        __syncthreads();
        const uint32_t base = sb + (ch & 1) * BUFSZ;
        const uint32_t aAh = base, aAl = base + ABYTES;
        const uint32_t aBh = base + 2 * ABYTES, aBl = base + 3 * ABYTES;
#pragma unroll
        for (int k = 0; k < 4; k++) {
            uint32_t ah[4][4], al[4][4], bh[4][2], bl[4][2];
#pragma unroll
            for (int mt = 0; mt < 4; mt++) {
                uint32_t off = (uint32_t)(((co0 + mt * 16 + (lane & 15)) * 72 +
                                           k * 16 + (lane >> 4) * 8) * 2);
                ldmat4(ah[mt][0], ah[mt][1], ah[mt][2], ah[mt][3], aAh + off);
                ldmat4(al[mt][0], al[mt][1], al[mt][2], al[mt][3], aAl + off);
            }
#pragma unroll
            for (int nt = 0; nt < 4; nt++) {
                uint32_t off = (uint32_t)(((p0l + nt * 8 + (lane & 7)) * 72 +
                                           k * 16 + ((lane >> 3) & 1) * 8) * 2);
                ldmat2(bh[nt][0], bh[nt][1], aBh + off);
                ldmat2(bl[nt][0], bl[nt][1], aBl + off);
            }
#pragma unroll
            for (int mt = 0; mt < 4; mt++)
#pragma unroll
                for (int nt = 0; nt < 4; nt++)
                    mma16816(acc[mt][nt], ah[mt], bh[nt]);
#pragma unroll
            for (int mt = 0; mt < 4; mt++)
#pragma unroll
                for (int nt = 0; nt < 4; nt++)
                    mma16816(acc[mt][nt], ah[mt], bl[nt]);
#pragma unroll
            for (int mt = 0; mt < 4; mt++)
#pragma unroll
                for (int nt = 0; nt < 4; nt++)
                    mma16816(acc[mt][nt], al[mt], bh[nt]);
        }
        __syncthreads();
    }

    float* lp = g_lp + ((size_t)lc * 16 + bn) * CO * CO;
#pragma unroll
    for (int mt = 0; mt < 4; mt++) {
        int c = co0 + mt * 16 + (lane >> 2);
#pragma unroll
        for (int nt = 0; nt < 4; nt++) {
            int m = p0l + nt * 8 + (lane & 3) * 2;
            *(float2*)(lp + (size_t)c * CO + m) =
                make_float2(acc[mt][nt][0], acc[mt][nt][1]);
            *(float2*)(lp + (size_t)(c + 8) * CO + m) =
                make_float2(acc[mt][nt][2], acc[mt][nt][3]);
        }
    }
}

// ---------------- softmax: reduce partials, emit split fp16 attn -----------
__global__ __launch_bounds__(256) void softmax_k() {
    const int warp = (blockIdx.x * 256 + threadIdx.x) >> 5;
    const int lane = threadIdx.x & 31;
    if (warp >= 16 * CO) return;
    const int bn = warp >> 7, c = warp & 127;
    float v[4];
#pragma unroll
    for (int j = 0; j < 4; j++) {
        int m = lane + j * 32;
        float s = 0.f;
#pragma unroll
        for (int p = 0; p < 9; p++)
            s += g_lp[(((size_t)p * 16 + bn) * CO + c) * CO + m];
        v[j] = s;
    }
    float mx = fmaxf(fmaxf(v[0], v[1]), fmaxf(v[2], v[3]));
#pragma unroll
    for (int o = 16; o; o >>= 1) mx = fmaxf(mx, __shfl_xor_sync(0xffffffffu, mx, o));
    float sum = 0.f;
#pragma unroll
    for (int j = 0; j < 4; j++) { v[j] = __expf(v[j] - mx); sum += v[j]; }
#pragma unroll
    for (int o = 16; o; o >>= 1) sum += __shfl_xor_sync(0xffffffffu, sum, o);
    float inv = 1.f / sum;
#pragma unroll
    for (int j = 0; j < 4; j++) {
        float a = v[j] * inv;
        __half h = __float2half_rn(a);
        size_t o = ((size_t)bn * CO + c) * CO + lane + j * 32;
        g_aH[o] = h;
        g_aL[o] = __float2half_rn(a - __half2float(h));
    }
}

// ---------------- out: attn x V via HMMA -----------------------------------
#define OPITCH 272
#define OTILE  34816
#define OSMEM  (4*OTILE)

__global__ __launch_bounds__(256, 1) void out2_k(float* __restrict__ out) {
    extern __shared__ char smem[];
    const uint32_t sb = smem_u32(smem);
    const int tid = threadIdx.x, wid = tid >> 5, lane = tid & 31;
    const int pt = blockIdx.x, b = blockIdx.y;
    const int l = pt >> 3;
    const int hw0 = (pt & 7) * 128;
    const int bn = b * 2 + (l >> 3);

    {
        int plane = tid >> 7, c = tid & 127;
        const __half* s =
            (plane ? g_aL : g_aH) + ((size_t)bn * CO + c) * CO;
        uint32_t dst = sb + plane * OTILE + c * OPITCH;
#pragma unroll
        for (int j = 0; j < 16; j++)
            cpasync16(dst + j * 16, (const char*)s + j * 16, 16);
        const __half* sv =
            (plane ? g_Vl : g_Vh) + ((size_t)(b * CO + c) * LV + l) * HW + hw0;
        uint32_t dv = sb + 2 * OTILE + plane * OTILE + c * OPITCH;
#pragma unroll
        for (int j = 0; j < 16; j++)
            cpasync16(dv + j * 16, (const char*)sv + j * 16, 16);
    }
    cp_commit();
    cp_wait0();
    __syncthreads();

    const int co0 = (wid & 1) * 64;
    const int p0l = (wid >> 1) * 32;
    const uint32_t aAh = sb, aAl = sb + OTILE;
    const uint32_t aBh = sb + 2 * OTILE, aBl = sb + 3 * OTILE;

    float acc[4][4][4];
#pragma unroll
    for (int mt = 0; mt < 4; mt++)
#pragma unroll
        for (int nt = 0; nt < 4; nt++)
#pragma unroll
            for (int i = 0; i < 4; i++) acc[mt][nt][i] = 0.f;

#pragma unroll
    for (int kc = 0; kc < 8; kc++) {
        uint32_t ah[4][4], al[4][4], bh[4][2], bl[4][2];
#pragma unroll
        for (int mt = 0; mt < 4; mt++) {
            uint32_t off = (uint32_t)((co0 + mt * 16 + (lane & 15)) * OPITCH +
                                      kc * 32 + (lane >> 4) * 16);
            ldmat4(ah[mt][0], ah[mt][1], ah[mt][2], ah[mt][3], aAh + off);
            ldmat4(al[mt][0], al[mt][1], al[mt][2], al[mt][3], aAl + off);
        }
#pragma unroll
        for (int nt = 0; nt < 4; nt++) {
            uint32_t off = (uint32_t)((kc * 16 + (lane & 15)) * OPITCH +
                                      (p0l + nt * 8) * 2);
            ldmat2t(bh[nt][0], bh[nt][1], aBh + off);
            ldmat2t(bl[nt][0], bl[nt][1], aBl + off);
        }
#pragma unroll
        for (int mt = 0; mt < 4; mt++)
#pragma unroll
            for (int nt = 0; nt < 4; nt++)
                mma16816(acc[mt][nt], ah[mt], bh[nt]);
#pragma unroll
        for (int mt = 0; mt < 4; mt++)
#pragma unroll
            for (int nt = 0; nt < 4; nt++)
                mma16816(acc[mt][nt], ah[mt], bl[nt]);
#pragma unroll
        for (int mt = 0; mt < 4; mt++)
#pragma unroll
            for (int nt = 0; nt < 4; nt++)
                mma16816(acc[mt][nt], al[mt], bh[nt]);
    }

#pragma unroll
    for (int mt = 0; mt < 4; mt++) {
        int c = co0 + mt * 16 + (lane >> 2);
        float* o0 = out + ((size_t)(b * CO + c) * LV + l) * HW + hw0 + p0l;
        float* o1 = o0 + (size_t)8 * LV * HW;
#pragma unroll
        for (int nt = 0; nt < 4; nt++) {
            int p = nt * 8 + (lane & 3) * 2;
            *(float2*)(o0 + p) = make_float2(acc[mt][nt][0], acc[mt][nt][1]);
            *(float2*)(o1 + p) = make_float2(acc[mt][nt][2], acc[mt][nt][3]);
        }
    }
}

// ---------------------------------------------------------------------------
extern "C" void kernel_launch(void* const* d_in, const int* in_sizes, int n_in,
                              void* d_out, int out_size) {
    const float* input  = (const float*)d_in[0];
    const float* memory = (const float*)d_in[1];
    const float* wq = (const float*)d_in[2];
    const float* bq = (const float*)d_in[3];
    const float* wk = (const float*)d_in[4];
    const float* bk = (const float*)d_in[5];
    const float* wv = (const float*)d_in[6];
    const float* bv = (const float*)d_in[7];
    float* out = (float*)d_out;

    cudaFuncSetAttribute(convmma_k<3>, cudaFuncAttributeMaxDynamicSharedMemorySize,
                         SMEMSZ);
    cudaFuncSetAttribute(convmma_k<2>, cudaFuncAttributeMaxDynamicSharedMemorySize,
                         SMEMSZ);
    cudaFuncSetAttribute(logits2_k, cudaFuncAttributeMaxDynamicSharedMemorySize,
                         SMEMSZ);
    cudaFuncSetAttribute(out2_k, cudaFuncAttributeMaxDynamicSharedMemorySize,
                         OSMEM);

    pack_k<<<dim3(BB * LL, 16), 256>>>(input, 0);
    pack_k<<<dim3(BB * LL, 16), 256>>>(memory, 1);
    wprep_k<<<(9 * 8192 + 255) / 256, 256>>>(wq, 9, 0);
    wprep_k<<<(9 * 8192 + 255) / 256, 256>>>(wk, 9, 1);
    wprep_k<<<(27 * 8192 + 255) / 256, 256>>>(wv, 27, 2);

    convmma_k<3><<<dim3(8, BB * LL), 256, SMEMSZ>>>(bq, 0, LL, 9, 0, 0.5f);
    convmma_k<3><<<dim3(8, BB * LL), 256, SMEMSZ>>>(bk, 1, LL, 9, 0, 1.0f);
    convmma_k<2><<<dim3(8, BB * LV), 256, SMEMSZ>>>(bv, 2, LV, 27, 1, 1.0f);

    logits2_k<<<dim3(9, 16), 256, SMEMSZ>>>();
    softmax_k<<<256, 256>>>();
    out2_k<<<dim3(128, 8), 256, OSMEM>>>(out);
}